// round 15
// baseline (speedup 1.0000x reference)
#include <cuda_runtime.h>

#define NN  100000
#define EE  1200000
#define HIDN 64
#define NHD 4
#define DHD 16
#define NLY 3
#define SCAN_B 1024
#define SCAN_G ((NN + SCAN_B - 1) / SCAN_B)   // 98
#define NPB 16                                 // nodes (warps) per block (edge kernel)
#define TPB (NPB * 32)                         // 512 threads
#define FULLM 0xffffffffu
#define MT 64                                  // GEMM tile: 64 nodes x 64 ch
#define GB ((NN + MT - 1) / MT)                // 1563 tiles

// packed f32x2 helpers (bit-identical to scalar fma.rn per lane)
#define PACKF(out, f) \
    asm("mov.b64 %0, {%1, %2};" : "=l"(out) : "r"(__float_as_uint(f)), "r"(__float_as_uint(f)))
#define UNPACKF(lo, hi, in) do { unsigned _ulo, _uhi; \
    asm("mov.b64 {%0, %1}, %2;" : "=r"(_ulo), "=r"(_uhi) : "l"(in)); \
    lo = __uint_as_float(_ulo); hi = __uint_as_float(_uhi); } while (0)
#define FMA2(d, a, b, c) \
    asm("fma.rn.f32x2 %0, %1, %2, %3;" : "=l"(d) : "l"(a), "l"(b), "l"(c))
#define ADD2(d, a, b) \
    asm("add.rn.f32x2 %0, %1, %2;" : "=l"(d) : "l"(a), "l"(b))

// ---- scratch (static device globals) ----
__device__ float g_h[NN * HIDN];        // node features between layers
__device__ float g_hw0[NN * HIDN];      // transformed features (ping)
__device__ float g_hw1[NN * HIDN];      // transformed features (pong)
__device__ float g_as0[NN * NHD], g_ad0[NN * NHD];
__device__ float g_as1[NN * NHD], g_ad1[NN * NHD];
__device__ float g_c0[NLY * NHD], g_c1[NLY * NHD];
// CSR by destination: packed (src, ea-bits)
__device__ int   g_deg[NN];
__device__ int   g_rs[NN];              // block-local exclusive prefix
__device__ int   g_cur[NN];
__device__ int2  g_cse[EE];
__device__ int   g_psum[SCAN_G];        // after k_scan: global exclusive block offsets
__device__ int   g_done;

// ---------------------------------------------------------------------------
// Init: zero deg/cur/done, and compute edge-attn constants (rank-1 edge path:
// a_e[e,h] = ea[e]*c1[l,h] + c0[l,h]) in the first NLY blocks.
// ---------------------------------------------------------------------------
__global__ void k_init(const float* __restrict__ w_ee, const float* __restrict__ b_ee,
                       const float* __restrict__ w_eg, const float* __restrict__ att_e)
{
    int gid = blockIdx.x * blockDim.x + threadIdx.x;
    if (gid < NN) g_deg[gid] = 0;
    else if (gid < 2 * NN) g_cur[gid - NN] = 0;
    if (gid == 2 * NN) g_done = 0;

    if (blockIdx.x < NLY) {
        __shared__ float sU[HIDN], sV[HIDN];
        int l = blockIdx.x, j = threadIdx.x;
        if (j < HIDN) {
            const float* W = w_eg + l * HIDN * HIDN;
            float U = 0.f, V = 0.f;
            for (int k = 0; k < HIDN; k++) {
                float wk = W[k * HIDN + j];
                U += w_ee[k] * wk;
                V += b_ee[k] * wk;
            }
            sU[j] = U; sV[j] = V;
        }
        __syncthreads();
        if (j < NHD) {
            float c1 = 0.f, c0 = 0.f;
            for (int d = 0; d < DHD; d++) {
                float a = att_e[l * HIDN + j * DHD + d];
                c1 += sU[j * DHD + d] * a;
                c0 += sV[j * DHD + d] * a;
            }
            g_c1[l * NHD + j] = c1;
            g_c0[l * NHD + j] = c0;
        }
    }
}

__global__ void k_count(const int* __restrict__ ei)
{
    int e = blockIdx.x * blockDim.x + threadIdx.x;
    if (e < EE) atomicAdd(&g_deg[ei[EE + e]], 1);
}

// ---------------------------------------------------------------------------
// Fused scan: per-block exclusive scan of deg -> rs, block totals -> psum;
// LAST block (ticket) then exclusive-scans psum in place.
// Consumers compute global base = rs[n] + psum[n>>10].
// ---------------------------------------------------------------------------
__global__ void k_scan()
{
    __shared__ int s[SCAN_B];
    __shared__ int ticket;
    int t = threadIdx.x, gid = blockIdx.x * SCAN_B + t;
    int v = (gid < NN) ? g_deg[gid] : 0;
    s[t] = v;
    __syncthreads();
    #pragma unroll
    for (int off = 1; off < SCAN_B; off <<= 1) {
        int u = (t >= off) ? s[t - off] : 0;
        __syncthreads();
        s[t] += u;
        __syncthreads();
    }
    if (gid < NN) g_rs[gid] = s[t] - v;            // exclusive within block
    if (t == SCAN_B - 1) g_psum[blockIdx.x] = s[t];

    __threadfence();
    __syncthreads();
    if (t == 0) ticket = atomicAdd(&g_done, 1);
    __syncthreads();
    if (ticket != SCAN_G - 1) return;

    // last block: exclusive scan of psum (98 entries)
    int pv = (t < SCAN_G) ? g_psum[t] : 0;
    s[t] = pv;
    __syncthreads();
    #pragma unroll
    for (int off = 1; off < 128; off <<= 1) {
        int u = (t >= off && t < SCAN_G) ? s[t - off] : 0;
        __syncthreads();
        if (t < SCAN_G) s[t] += u;
        __syncthreads();
    }
    if (t < SCAN_G) g_psum[t] = s[t] - pv;
}

__global__ void k_scatter(const int* __restrict__ ei, const float* __restrict__ ea)
{
    int e = blockIdx.x * blockDim.x + threadIdx.x;
    if (e >= EE) return;
    int dst = ei[EE + e];
    int pos = g_rs[dst] + g_psum[dst >> 10] + atomicAdd(&g_cur[dst], 1);
    g_cse[pos] = make_int2(ei[e], __float_as_int(ea[e]));
}

// ---------------------------------------------------------------------------
// Edge aggregation + node update: one warp per dst node.
// lane = slot*8 + t; 4 edge slots, lane t owns channels t*8..t*8+7.
// Uniform skip of the second 4-edge half when past dg. f32x2 accumulate.
// Then normalize + bias + ELU + residual + LayerNorm -> g_h in place.
// ---------------------------------------------------------------------------
__global__ void __launch_bounds__(TPB, 2)
k_edge_agg(const float* __restrict__ hw_in,
           const float* __restrict__ as_in, const float* __restrict__ ad_in,
           int l,
           const float* __restrict__ b_gat,
           const float* __restrict__ lng, const float* __restrict__ lnb)
{
    __shared__ float tb[NPB][HIDN];
    int tid = threadIdx.x;
    int warp = tid >> 5, lane = tid & 31;
    int n = blockIdx.x * NPB + warp;
    if (n >= NN) return;

    int t    = lane & 7;                     // channel-slice owner (0..7)
    int slot = lane >> 3;                    // edge slot (0..3)
    int head = t >> 1;                       // head of channels t*8..t*8+7
    float c1h = g_c1[l * NHD + head], c0h = g_c0[l * NHD + head];
    float adh = ad_in[n * NHD + head];
    int base = g_rs[n] + g_psum[n >> 10];
    int dg   = g_deg[n];

    const float4* as4 = (const float4*)as_in;

    unsigned long long acc2[4] = {0ull, 0ull, 0ull, 0ull};
    float den = 0.f;

    for (int off = 0; off < dg; off += 8) {
        {   // half A: edges off+slot (predicated per-lane)
            int idx = off + slot;
            bool v = idx < dg;
            int2 se = g_cse[base + (v ? idx : 0)];
            int src = v ? se.x : 0;
            float4 av = as4[src];
            float asv = (head == 0) ? av.x : (head == 1) ? av.y
                      : (head == 2) ? av.z : av.w;
            float s = asv + adh + __int_as_float(se.y) * c1h + c0h;
            s = (s > 0.f) ? s : 0.2f * s;
            float ex = v ? __expf(s) : 0.f;
            den += ex;
            unsigned long long exp2v; PACKF(exp2v, ex);
            const ulonglong2* hp = (const ulonglong2*)(hw_in + src * HIDN + t * 8);
            ulonglong2 P = hp[0], Q = hp[1];
            FMA2(acc2[0], exp2v, P.x, acc2[0]);
            FMA2(acc2[1], exp2v, P.y, acc2[1]);
            FMA2(acc2[2], exp2v, Q.x, acc2[2]);
            FMA2(acc2[3], exp2v, Q.y, acc2[3]);
        }
        if (off + 4 < dg) {   // half B: uniform skip (dg warp-uniform)
            int idx = off + 4 + slot;
            bool v = idx < dg;
            int2 se = g_cse[base + (v ? idx : 0)];
            int src = v ? se.x : 0;
            float4 av = as4[src];
            float asv = (head == 0) ? av.x : (head == 1) ? av.y
                      : (head == 2) ? av.z : av.w;
            float s = asv + adh + __int_as_float(se.y) * c1h + c0h;
            s = (s > 0.f) ? s : 0.2f * s;
            float ex = v ? __expf(s) : 0.f;
            den += ex;
            unsigned long long exp2v; PACKF(exp2v, ex);
            const ulonglong2* hp = (const ulonglong2*)(hw_in + src * HIDN + t * 8);
            ulonglong2 P = hp[0], Q = hp[1];
            FMA2(acc2[0], exp2v, P.x, acc2[0]);
            FMA2(acc2[1], exp2v, P.y, acc2[1]);
            FMA2(acc2[2], exp2v, Q.x, acc2[2]);
            FMA2(acc2[3], exp2v, Q.y, acc2[3]);
        }
    }

    // reduce over the 4 edge slots (lanes differing in bits 3,4)
    #pragma unroll
    for (int i = 0; i < 4; i++) {
        unsigned long long o8  = __shfl_xor_sync(FULLM, acc2[i], 8);
        ADD2(acc2[i], acc2[i], o8);
        unsigned long long o16 = __shfl_xor_sync(FULLM, acc2[i], 16);
        ADD2(acc2[i], acc2[i], o16);
    }
    den += __shfl_xor_sync(FULLM, den, 8);
    den += __shfl_xor_sync(FULLM, den, 16);

    // transpose to 2-channels-per-lane layout via per-warp smem buffer
    if (lane < 8) {
        float f0, f1, f2, f3, f4, f5, f6, f7;
        UNPACKF(f0, f1, acc2[0]);
        UNPACKF(f2, f3, acc2[1]);
        UNPACKF(f4, f5, acc2[2]);
        UNPACKF(f6, f7, acc2[3]);
        float4* tp = (float4*)&tb[warp][lane * 8];
        tp[0] = make_float4(f0, f1, f2, f3);
        tp[1] = make_float4(f4, f5, f6, f7);
    }
    __syncwarp();
    float num0 = tb[warp][lane];
    float num1 = tb[warp][lane + 32];
    float d0 = __shfl_sync(FULLM, den, 2 * (lane >> 4));
    float d1 = __shfl_sync(FULLM, den, 4 + 2 * (lane >> 4));

    float v0 = num0 / (d0 + 1e-16f) + b_gat[l * HIDN + lane];
    float v1 = num1 / (d1 + 1e-16f) + b_gat[l * HIDN + lane + 32];
    v0 = (v0 > 0.f) ? v0 : expm1f(v0);
    v1 = (v1 > 0.f) ? v1 : expm1f(v1);

    float x0 = g_h[n * HIDN + lane]      + v0;
    float x1 = g_h[n * HIDN + lane + 32] + v1;

    float s = x0 + x1;
    #pragma unroll
    for (int o = 16; o; o >>= 1) s += __shfl_xor_sync(FULLM, s, o);
    float mean = s * (1.f / 64.f);
    float vv = (x0 - mean) * (x0 - mean) + (x1 - mean) * (x1 - mean);
    #pragma unroll
    for (int o = 16; o; o >>= 1) vv += __shfl_xor_sync(FULLM, vv, o);
    float inv = rsqrtf(vv * (1.f / 64.f) + 1e-5f);

    g_h[n * HIDN + lane]      = (x0 - mean) * inv * lng[l * HIDN + lane]      + lnb[l * HIDN + lane];
    g_h[n * HIDN + lane + 32] = (x1 - mean) * inv * lng[l * HIDN + lane + 32] + lnb[l * HIDN + lane + 32];
}

// ---------------------------------------------------------------------------
// Tiled projection GEMM: out[64-node tile][64] = h @ W (+bias).
// 256 threads, per-thread 4x4, k blocked by 4, f32x2 packed FMA.
// mode 0: write hw + attention dots (as/ad).
// mode 1: write o = h@W + bias.
// mode 2: like mode 1 but h computed on the fly: relu(x@w1 + b1), x=[N,6].
// ---------------------------------------------------------------------------
__global__ void __launch_bounds__(256)
k_project(const float* __restrict__ h, const float* __restrict__ W,
          const float* __restrict__ attS, const float* __restrict__ attD,
          const float* __restrict__ bias,
          const float* __restrict__ w1, const float* __restrict__ b1,
          float* __restrict__ o, float* __restrict__ as_o, float* __restrict__ ad_o,
          int mode)
{
    __shared__ float hs[MT][HIDN + 4];   // [m][k], rows 272B (16B aligned)
    __shared__ float ws[HIDN][HIDN + 4]; // [k][c]
    __shared__ float sa[HIDN], sd[HIDN];
    __shared__ float w1s[6][HIDN];
    __shared__ float b1s[HIDN];
    int tid = threadIdx.x;
    int m0 = blockIdx.x * MT;

    if (mode == 2) {
        for (int i = tid; i < 6 * HIDN; i += 256)
            w1s[i / HIDN][i % HIDN] = w1[i];
        if (tid < HIDN) b1s[tid] = b1[tid];
    }
    // stage W (k-major rows)
    for (int i = tid; i < HIDN * 16; i += 256) {
        int k = i >> 4, cq = i & 15;
        *(float4*)&ws[k][cq * 4] = *(const float4*)(W + k * HIDN + cq * 4);
    }
    if (mode == 0 && tid < HIDN) { sa[tid] = attS[tid]; sd[tid] = attD[tid]; }
    if (mode == 2) __syncthreads();      // w1s ready before hs compute

    // stage h [m][k] (vectorized)
    for (int i = tid; i < MT * 16; i += 256) {
        int m = i >> 4, kq = i & 15;
        float4 v;
        if (mode == 2) {
            v = make_float4(0.f, 0.f, 0.f, 0.f);
            if (m0 + m < NN) {
                float xv[6];
                #pragma unroll
                for (int k = 0; k < 6; k++) xv[k] = h[(size_t)(m0 + m) * 6 + k];
                v = *(const float4*)&b1s[kq * 4];
                #pragma unroll
                for (int k = 0; k < 6; k++) {
                    const float* wr = &w1s[k][kq * 4];
                    v.x += xv[k] * wr[0];
                    v.y += xv[k] * wr[1];
                    v.z += xv[k] * wr[2];
                    v.w += xv[k] * wr[3];
                }
                v.x = fmaxf(v.x, 0.f); v.y = fmaxf(v.y, 0.f);
                v.z = fmaxf(v.z, 0.f); v.w = fmaxf(v.w, 0.f);
            }
        } else {
            v = (m0 + m < NN) ? *(const float4*)(h + (size_t)(m0 + m) * HIDN + kq * 4)
                              : make_float4(0.f, 0.f, 0.f, 0.f);
        }
        *(float4*)&hs[m][kq * 4] = v;
    }
    __syncthreads();

    int tx = tid & 15, ty = tid >> 4;        // tx: 4-ch group, ty: 4-node group
    unsigned long long a2[4][2];
    #pragma unroll
    for (int i = 0; i < 4; i++) { a2[i][0] = 0ull; a2[i][1] = 0ull; }

    #pragma unroll
    for (int k4 = 0; k4 < 16; k4++) {
        float4 hv0 = *(const float4*)&hs[ty * 4 + 0][k4 * 4];
        float4 hv1 = *(const float4*)&hs[ty * 4 + 1][k4 * 4];
        float4 hv2 = *(const float4*)&hs[ty * 4 + 2][k4 * 4];
        float4 hv3 = *(const float4*)&hs[ty * 4 + 3][k4 * 4];
        float h0[4] = {hv0.x, hv0.y, hv0.z, hv0.w};
        float h1[4] = {hv1.x, hv1.y, hv1.z, hv1.w};
        float h2[4] = {hv2.x, hv2.y, hv2.z, hv2.w};
        float h3[4] = {hv3.x, hv3.y, hv3.z, hv3.w};
        #pragma unroll
        for (int kk = 0; kk < 4; kk++) {
            ulonglong2 w = *(const ulonglong2*)&ws[k4 * 4 + kk][tx * 4];
            unsigned long long p0, p1, p2, p3;
            PACKF(p0, h0[kk]); PACKF(p1, h1[kk]);
            PACKF(p2, h2[kk]); PACKF(p3, h3[kk]);
            FMA2(a2[0][0], p0, w.x, a2[0][0]); FMA2(a2[0][1], p0, w.y, a2[0][1]);
            FMA2(a2[1][0], p1, w.x, a2[1][0]); FMA2(a2[1][1], p1, w.y, a2[1][1]);
            FMA2(a2[2][0], p2, w.x, a2[2][0]); FMA2(a2[2][1], p2, w.y, a2[2][1]);
            FMA2(a2[3][0], p3, w.x, a2[3][0]); FMA2(a2[3][1], p3, w.y, a2[3][1]);
        }
    }

    float acc[4][4];
    #pragma unroll
    for (int mi = 0; mi < 4; mi++) {
        UNPACKF(acc[mi][0], acc[mi][1], a2[mi][0]);
        UNPACKF(acc[mi][2], acc[mi][3], a2[mi][1]);
    }

    if (mode != 0) {
        float4 bv = *(const float4*)(bias + tx * 4);
        #pragma unroll
        for (int mi = 0; mi < 4; mi++) {
            int n = m0 + ty * 4 + mi;
            if (n < NN)
                *(float4*)(o + (size_t)n * HIDN + tx * 4) =
                    make_float4(acc[mi][0] + bv.x, acc[mi][1] + bv.y,
                                acc[mi][2] + bv.z, acc[mi][3] + bv.w);
        }
        return;
    }

    // mode 0: store hw + attention dots
    #pragma unroll
    for (int mi = 0; mi < 4; mi++) {
        int n = m0 + ty * 4 + mi;
        if (n < NN)
            *(float4*)(o + (size_t)n * HIDN + tx * 4) =
                make_float4(acc[mi][0], acc[mi][1], acc[mi][2], acc[mi][3]);
    }
    // dots: channels tx*4..tx*4+3 all lie in head tx>>2
    float4 sav = *(float4*)&sa[tx * 4];
    float4 sdv = *(float4*)&sd[tx * 4];
    #pragma unroll
    for (int mi = 0; mi < 4; mi++) {
        float ps = acc[mi][0] * sav.x + acc[mi][1] * sav.y
                 + acc[mi][2] * sav.z + acc[mi][3] * sav.w;
        float pd = acc[mi][0] * sdv.x + acc[mi][1] * sdv.y
                 + acc[mi][2] * sdv.z + acc[mi][3] * sdv.w;
        // reduce over the 4 tx's of this head (lane bits 0,1)
        ps += __shfl_xor_sync(FULLM, ps, 1);
        ps += __shfl_xor_sync(FULLM, ps, 2);
        pd += __shfl_xor_sync(FULLM, pd, 1);
        pd += __shfl_xor_sync(FULLM, pd, 2);
        int n = m0 + ty * 4 + mi;
        if ((tx & 3) == 0 && n < NN) {
            as_o[n * NHD + (tx >> 2)] = ps;
            ad_o[n * NHD + (tx >> 2)] = pd;
        }
    }
}

// ---------------------------------------------------------------------------
extern "C" void kernel_launch(void* const* d_in, const int* in_sizes, int n_in,
                              void* d_out, int out_size)
{
    const float* x        = (const float*)d_in[0];
    const int*   ei       = (const int*)d_in[1];     // int64 in ref -> int32 on device
    const float* ea       = (const float*)d_in[2];
    const float* w_ne1    = (const float*)d_in[3];
    const float* b_ne1    = (const float*)d_in[4];
    const float* w_ne2    = (const float*)d_in[5];
    const float* b_ne2    = (const float*)d_in[6];
    const float* w_ee     = (const float*)d_in[7];
    const float* b_ee     = (const float*)d_in[8];
    const float* w_gat    = (const float*)d_in[9];
    const float* w_eg     = (const float*)d_in[10];
    const float* att_src  = (const float*)d_in[11];
    const float* att_dst  = (const float*)d_in[12];
    const float* att_edge = (const float*)d_in[13];
    const float* b_gat    = (const float*)d_in[14];
    const float* ln_g     = (const float*)d_in[15];
    const float* ln_b     = (const float*)d_in[16];
    const float* w_out    = (const float*)d_in[17];
    const float* b_out    = (const float*)d_in[18];
    float*       out      = (float*)d_out;

    int nb = (NN + NPB - 1) / NPB;
    int eb = (EE + 255) / 256;
    int ib = (2 * NN + 256) / 256;

    float* g_hp;    cudaGetSymbolAddress((void**)&g_hp,   g_h);
    float* g_hw0p;  cudaGetSymbolAddress((void**)&g_hw0p, g_hw0);
    float* g_hw1p;  cudaGetSymbolAddress((void**)&g_hw1p, g_hw1);
    float* g_as0p;  cudaGetSymbolAddress((void**)&g_as0p, g_as0);
    float* g_ad0p;  cudaGetSymbolAddress((void**)&g_ad0p, g_ad0);
    float* g_as1p;  cudaGetSymbolAddress((void**)&g_as1p, g_as1);
    float* g_ad1p;  cudaGetSymbolAddress((void**)&g_ad1p, g_ad1);

    // CSR build + constants: 4 launches
    k_init<<<ib, 256>>>(w_ee, b_ee, w_eg, att_edge);
    k_count<<<eb, 256>>>(ei);
    k_scan<<<SCAN_G, SCAN_B>>>();
    k_scatter<<<eb, 256>>>(ei, ea);

    // encoder fused: h = relu(x w1 + b1) w2 + b2   (mode 2)  -- launch #5
    k_project<<<GB, 256>>>(x, w_ne2, nullptr, nullptr, b_ne2, w_ne1, b_ne1,
                           g_hp, nullptr, nullptr, 2);
    // layer-0 transform (mode 0)                             -- launch #6 (ncu -s 5 target)
    k_project<<<GB, 256>>>(g_hp, w_gat, att_src, att_dst, nullptr, nullptr, nullptr,
                           g_hw0p, g_as0p, g_ad0p, 0);

    // layer 0
    k_edge_agg<<<nb, TPB>>>(g_hw0p, g_as0p, g_ad0p, 0, b_gat, ln_g, ln_b);
    k_project<<<GB, 256>>>(g_hp, w_gat + 1 * HIDN * HIDN,
                           att_src + 1 * NHD * DHD, att_dst + 1 * NHD * DHD,
                           nullptr, nullptr, nullptr,
                           g_hw1p, g_as1p, g_ad1p, 0);
    // layer 1
    k_edge_agg<<<nb, TPB>>>(g_hw1p, g_as1p, g_ad1p, 1, b_gat, ln_g, ln_b);
    k_project<<<GB, 256>>>(g_hp, w_gat + 2 * HIDN * HIDN,
                           att_src + 2 * NHD * DHD, att_dst + 2 * NHD * DHD,
                           nullptr, nullptr, nullptr,
                           g_hw0p, g_as0p, g_ad0p, 0);
    // layer 2 + output projection
    k_edge_agg<<<nb, TPB>>>(g_hw0p, g_as0p, g_ad0p, 2, b_gat, ln_g, ln_b);
    k_project<<<GB, 256>>>(g_hp, w_out, nullptr, nullptr, b_out, nullptr, nullptr,
                           out, nullptr, nullptr, 1);
}